// round 12
// baseline (speedup 1.0000x reference)
#include <cuda_runtime.h>
#include <cuda_fp16.h>
#include <math.h>
#include <stdint.h>

#define SS 1024
#define DD 1024
#define HH 16
#define HDIM 64
#define FFDIM 4096
#define NROW 4096      // B*S
#define D1 1025
#define HD1 65
#define BHN 64         // B*H
#define CATW 1040      // H*(HD+1)
#define EP 80          // padded head-dim+1 (65 -> 80)
#define VE 80          // e-major V rows (65 data + 15 zero pad)

#define KP1 1088       // padded K (17*64)
#define KP2 4160       // padded K (65*64)

// ---------------- scratch (device globals; no allocation allowed) ----------
__device__ float g_qkv[NROW * 3072];
__device__ float g_tmp[NROW * DD];
__device__ float g_x2 [NROW * D1];

// fp16 buffers (single-term everywhere)
__device__ __align__(16) __half gA_hi [(size_t)NROW * KP1];
__device__ __align__(16) __half gA2_hi[(size_t)NROW * KP2];
__device__ __align__(16) __half gB_hi[(size_t)4096 * KP1];

// q (time-comp pre-negated), k: [bh][s][EP]
__device__ __align__(16) __half g_qh[(size_t)BHN * SS * EP];
__device__ __align__(16) __half g_kh[(size_t)BHN * SS * EP];

// V e-major: [bh][e(80)][s]
__device__ __align__(16) __half g_vh[(size_t)BHN * VE * SS];

// ---------------- small helpers ----------------------------------------------
__device__ __forceinline__ uint32_t smem_u32(const void* p) {
    uint32_t a;
    asm("{ .reg .u64 t; cvta.to.shared.u64 t, %1; cvt.u32.u64 %0, t; }"
        : "=r"(a) : "l"(p));
    return a;
}
__device__ __forceinline__ void cp_async16(uint32_t s, const void* g) {
    asm volatile("{ .reg .u64 gp; cvta.to.global.u64 gp, %1; "
                 "cp.async.cg.shared.global [%0], [gp], 16; }"
                 :: "r"(s), "l"(g) : "memory");
}
__device__ __forceinline__ void cp_commit() {
    asm volatile("cp.async.commit_group;" ::: "memory");
}
template<int N>
__device__ __forceinline__ void cp_wait() {
    asm volatile("cp.async.wait_group %0;" :: "n"(N) : "memory");
}
__device__ __forceinline__ void ldsm_x4(uint32_t* r, uint32_t addr) {
    asm volatile("ldmatrix.sync.aligned.m8n8.x4.shared.b16 {%0,%1,%2,%3}, [%4];"
                 : "=r"(r[0]), "=r"(r[1]), "=r"(r[2]), "=r"(r[3]) : "r"(addr));
}
__device__ __forceinline__ void mma_f16(float* c, const uint32_t* a, const uint32_t* b) {
    asm volatile("mma.sync.aligned.m16n8k16.row.col.f32.f16.f16.f32 "
                 "{%0,%1,%2,%3}, {%4,%5,%6,%7}, {%8,%9}, {%0,%1,%2,%3};"
                 : "+f"(c[0]), "+f"(c[1]), "+f"(c[2]), "+f"(c[3])
                 : "r"(a[0]), "r"(a[1]), "r"(a[2]), "r"(a[3]), "r"(b[0]), "r"(b[1]));
}
__device__ __forceinline__ uint32_t pack2h(float a, float b) {
    __half2 t;
    t.x = __float2half_rn(a);
    t.y = __float2half_rn(b);
    return *reinterpret_cast<uint32_t*>(&t);
}

// fast exp for logits in ~[-0.6, 0]
__device__ __forceinline__ float exp_fast(float x) {
    float t = fmaxf(x * 1.4426950408889634f, -100.f);
    float r = t + 12582912.0f;
    int ri = __float_as_int(r);
    float fi = r - 12582912.0f;
    float f = t - fi;
    float p = 0.00133335581f;
    p = fmaf(p, f, 0.00961812911f);
    p = fmaf(p, f, 0.05550410866f);
    p = fmaf(p, f, 0.24022650696f);
    p = fmaf(p, f, 0.69314718056f);
    p = fmaf(p, f, 1.0f);
    float s = __int_as_float((ri + 127) << 23);
    return p * s;
}

// ---------------- reductions --------------------------------------------------
__device__ __forceinline__ float blockReduceSum(float v, float* sm) {
    #pragma unroll
    for (int o = 16; o; o >>= 1) v += __shfl_xor_sync(0xffffffffu, v, o);
    int w = threadIdx.x >> 5;
    if ((threadIdx.x & 31) == 0) sm[w] = v;
    __syncthreads();
    if (threadIdx.x < 32) {
        float t = (threadIdx.x < 8) ? sm[threadIdx.x] : 0.f;
        #pragma unroll
        for (int o = 4; o; o >>= 1) t += __shfl_xor_sync(0xffffffffu, t, o);
        if (threadIdx.x == 0) sm[0] = t;
    }
    __syncthreads();
    float r = sm[0];
    __syncthreads();
    return r;
}
__device__ __forceinline__ float gelu_tanh(float x) {
    float x3 = x * x * x;
    float t = tanhf(0.7978845608028654f * (x + 0.044715f * x3));
    return 0.5f * x * (1.0f + t);
}

// ---------------- layernorm (writes fp16 gA_hi directly) ----------------------
__global__ void __launch_bounds__(256) ln_kernel(const float* __restrict__ Xext,
                                                 int useInternal,
                                                 const float* __restrict__ g,
                                                 const float* __restrict__ b) {
    __shared__ float sm[8];
    const float* X = useInternal ? g_x2 : Xext;
    int row = blockIdx.x;
    const float* xr = X + (size_t)row * D1 + 1;
    float v[4], s = 0.f, sq = 0.f;
    #pragma unroll
    for (int i = 0; i < 4; i++) {
        v[i] = xr[threadIdx.x + i * 256];
        s += v[i]; sq += v[i] * v[i];
    }
    s  = blockReduceSum(s,  sm);
    sq = blockReduceSum(sq, sm);
    float mu = s * (1.f / DD);
    float var = sq * (1.f / DD) - mu * mu;
    float rstd = rsqrtf(var + 1e-5f);
    float o[4], ss = 0.f;
    #pragma unroll
    for (int i = 0; i < 4; i++) {
        int c = threadIdx.x + i * 256;
        o[i] = (v[i] - mu) * rstd * g[c] + b[c];
        ss += o[i] * o[i];
    }
    ss = blockReduceSum(ss, sm);
    size_t ob = (size_t)row * KP1;
    if (threadIdx.x == 0)
        gA_hi[ob] = __float2half_rn(sqrtf(1.f + ss));
    #pragma unroll
    for (int i = 0; i < 4; i++)
        gA_hi[ob + 1 + threadIdx.x + i * 256] = __float2half_rn(o[i]);
    if (threadIdx.x < KP1 - 1025)
        gA_hi[ob + 1025 + threadIdx.x] = __float2half_rn(0.f);
}

// ---------------- weight transpose (fp16) -------------------------------------
__global__ void __launch_bounds__(256) transW_k(const float* __restrict__ src,
                                                int dstRow0, int K, int Kp,
                                                int strideK, int headStride,
                                                int headWidth) {
    __shared__ float t[32][33];
    int tx = threadIdx.x & 31, ty = threadIdx.x >> 5;
    int k0 = blockIdx.x * 32, n0 = blockIdx.y * 32;
    #pragma unroll
    for (int i = 0; i < 4; i++) {
        int k = k0 + ty + i * 8;
        int n = n0 + tx;
        float v = 0.f;
        if (k < K)
            v = src[(size_t)(n / headWidth) * headStride + (size_t)k * strideK + (n % headWidth)];
        t[ty + i * 8][tx] = v;
    }
    __syncthreads();
    #pragma unroll
    for (int i = 0; i < 4; i++) {
        int n = n0 + ty + i * 8;
        int k = k0 + tx;
        gB_hi[(size_t)(dstRow0 + n) * Kp + k] = __float2half_rn(t[tx][ty + i * 8]);
    }
}

// ---------------- warp-MMA fp16 GEMM (128x128 C tile, 3-stage) ----------------
#define TCS 16384
#define STG 32768
template<int EPI>
__global__ void __launch_bounds__(256, 1) mmagemm_k(
    int asel, int csel,
    const float* __restrict__ bias0, const float* __restrict__ bias1,
    const float* __restrict__ bias2,
    int Kp, int ldc, int nPerMat)
{
    extern __shared__ __align__(128) char dsm[];
    uint32_t sb0 = smem_u32(dsm);

    int tid = threadIdx.x;
    int wid = tid >> 5, lane = tid & 31;
    int wm = wid & 3, wn = wid >> 2;
    int m0 = blockIdx.y * 128, n0 = blockIdx.x * 128;

    int lchunk = tid & 7;
    int lrow = tid >> 3;

    const __half* Asrc = asel ? gA2_hi : gA_hi;
    const int NC = Kp >> 6;

    uint32_t aoff[2];
    {
        int khalf = lane >> 4;
        #pragma unroll
        for (int mi = 0; mi < 2; mi++) {
            int r = wm * 32 + mi * 16 + (lane & 15);
            aoff[mi] = (uint32_t)(r * 128) + (uint32_t)(((khalf) ^ (r & 7)) << 4);
        }
    }
    uint32_t boff[4];
    {
        int idx = lane >> 3;
        int khalf = idx & 1;
        #pragma unroll
        for (int jp = 0; jp < 4; jp++) {
            int r = wn * 64 + jp * 16 + (idx >> 1) * 8 + (lane & 7);
            boff[jp] = (uint32_t)(r * 128) + (uint32_t)((khalf ^ (r & 7)) << 4);
        }
    }

    float acc[2][8][4];
    #pragma unroll
    for (int i = 0; i < 2; i++)
        #pragma unroll
        for (int j = 0; j < 8; j++)
            #pragma unroll
            for (int q = 0; q < 4; q++) acc[i][j][q] = 0.f;

    auto load_stage = [&](int ic, int st) {
        size_t kbase = (size_t)ic * 64 + lchunk * 8;
        uint32_t sbase = sb0 + st * STG;
        #pragma unroll
        for (int i = 0; i < 4; i++) {
            int r = lrow + i * 32;
            uint32_t so = (uint32_t)(r * 128) + (uint32_t)((lchunk ^ (r & 7)) << 4);
            cp_async16(sbase + so, Asrc + (size_t)(m0 + r) * Kp + kbase);
            cp_async16(sbase + TCS + so, gB_hi + (size_t)(n0 + r) * Kp + kbase);
        }
        cp_commit();
    };

    load_stage(0, 0);
    if (NC > 1) load_stage(1, 1);

    int st = 0;
    for (int ic = 0; ic < NC; ic++) {
        if (ic + 2 < NC) {
            int st2 = (st + 2) % 3;
            load_stage(ic + 2, st2);
            cp_wait<2>();
        } else if (ic + 1 < NC) {
            cp_wait<1>();
        } else {
            cp_wait<0>();
        }
        __syncthreads();

        uint32_t aH = sb0 + st * STG;
        uint32_t bH = aH + TCS;

        #pragma unroll
        for (int ks = 0; ks < 4; ks++) {
            uint32_t kso = (uint32_t)(ks * 32);
            uint32_t Ah[2][4];
            #pragma unroll
            for (int mi = 0; mi < 2; mi++)
                ldsm_x4(Ah[mi], aH + (aoff[mi] ^ kso));
            uint32_t Bh[8][2];
            #pragma unroll
            for (int jp = 0; jp < 4; jp++) {
                uint32_t r4[4];
                ldsm_x4(r4, bH + (boff[jp] ^ kso));
                Bh[jp * 2][0] = r4[0]; Bh[jp * 2][1] = r4[1];
                Bh[jp * 2 + 1][0] = r4[2]; Bh[jp * 2 + 1][1] = r4[3];
            }
            #pragma unroll
            for (int mi = 0; mi < 2; mi++)
                #pragma unroll
                for (int nj = 0; nj < 8; nj++)
                    mma_f16(acc[mi][nj], Ah[mi], Bh[nj]);
        }
        __syncthreads();
        st = (st + 1) % 3;
    }

    int selB = (n0 / nPerMat);
    const float* bias = (selB == 0) ? bias0 : (selB == 1 ? bias1 : bias2);
    int nL0 = n0 - selB * nPerMat;

    int g = lane >> 2, t = lane & 3;
    if (csel == 2) {
        #pragma unroll
        for (int mi = 0; mi < 2; mi++) {
            int r0 = m0 + wm * 32 + mi * 16 + g;
            #pragma unroll
            for (int nj = 0; nj < 8; nj++) {
                int col = wn * 64 + nj * 8 + 2 * t;
                float b0 = bias[nL0 + col], b1 = bias[nL0 + col + 1];
                #pragma unroll
                for (int half = 0; half < 2; half++) {
                    float v0 = gelu_tanh(acc[mi][nj][half * 2 + 0] + b0);
                    float v1 = gelu_tanh(acc[mi][nj][half * 2 + 1] + b1);
                    size_t o = (size_t)(r0 + half * 8) * ldc + 1 + n0 + col;
                    gA2_hi[o] = __float2half_rn(v0);
                    gA2_hi[o + 1] = __float2half_rn(v1);
                }
            }
        }
    } else {
        float* C = (csel == 0) ? g_qkv : g_tmp;
        #pragma unroll
        for (int mi = 0; mi < 2; mi++) {
            int r0 = m0 + wm * 32 + mi * 16 + g;
            #pragma unroll
            for (int nj = 0; nj < 8; nj++) {
                int col = wn * 64 + nj * 8 + 2 * t;
                int cg = n0 + col;
                float b0 = bias[nL0 + col], b1 = bias[nL0 + col + 1];
                float* p0 = C + (size_t)r0 * ldc + cg;
                float* p1 = C + (size_t)(r0 + 8) * ldc + cg;
                p0[0] = acc[mi][nj][0] + b0; p0[1] = acc[mi][nj][1] + b1;
                p1[0] = acc[mi][nj][2] + b0; p1[1] = acc[mi][nj][3] + b1;
            }
        }
    }
}

// ---------------- RoPE + unit-norm + lift; q/k row-major, V e-major -----------
__global__ void __launch_bounds__(256) rope_k(const float* __restrict__ rc,
                                              const float* __restrict__ rs) {
    int gw = (blockIdx.x * 256 + threadIdx.x) >> 5;
    int lane = threadIdx.x & 31;
    int mat = gw / (NROW * HH);
    int rem = gw - mat * (NROW * HH);
    int row = rem >> 4;
    int h = rem & 15;
    int b = row >> 10, s = row & 1023;
    int bh = b * HH + h;
    const float* src = g_qkv + (size_t)row * 3072 + mat * 1024 + h * 64 + 2 * lane;
    float x0 = src[0], x1 = src[1];
    if (mat < 2) {
        float c = rc[s * 32 + lane], sn = rs[s * 32 + lane];
        float xr = x0 * c - x1 * sn;
        float xi = x0 * sn + x1 * c;
        float ss = xr * xr + xi * xi;
        #pragma unroll
        for (int o = 16; o; o >>= 1) ss += __shfl_xor_sync(0xffffffffu, ss, o);
        float inv = rsqrtf(ss + 1e-6f);
        float t = sqrtf(1.f + ss * inv * inv);
        __half* dh = ((mat == 0) ? g_qh : g_kh) + (size_t)(bh * SS + s) * EP;
        dh[1 + 2 * lane] = __float2half_rn(xr * inv);
        dh[2 + 2 * lane] = __float2half_rn(xi * inv);
        if (lane == 0) dh[0] = __float2half_rn((mat == 0) ? -t : t);
        if (lane < 15) dh[65 + lane] = __float2half_rn(0.f);
    } else {
        float ss = x0 * x0 + x1 * x1;
        #pragma unroll
        for (int o = 16; o; o >>= 1) ss += __shfl_xor_sync(0xffffffffu, ss, o);
        __half* vh = g_vh + (size_t)bh * VE * SS;
        vh[(size_t)(1 + 2 * lane) * SS + s] = __float2half_rn(x0);
        vh[(size_t)(2 + 2 * lane) * SS + s] = __float2half_rn(x1);
        if (lane == 0) vh[s] = __float2half_rn(sqrtf(1.f + ss));
        if (lane < 15) vh[(size_t)(65 + lane) * SS + s] = __float2half_rn(0.f);
    }
}

// ---------------- flash attention (single-term fp16) --------------------------
#define SROW 176
#define FQ_SZ  22528                  // Q (128 x 176B)
#define FK_HI  0
#define FV_HI  11264
#define F_STG  21504                  // K (64x176) + V (80x128)
__global__ void __launch_bounds__(256, 1) flash_k(const float* __restrict__ scale_p) {
    extern __shared__ __align__(128) char dsm[];
    uint32_t sb = smem_u32(dsm);

    int tid = threadIdx.x;
    int wid = tid >> 5, lane = tid & 31;
    int bh = blockIdx.y;
    int m0 = blockIdx.x * 128;
    size_t qkBase = (size_t)bh * SS;
    size_t vBase = (size_t)bh * VE * SS;

    // load Q (128 rows x 160B, stride 176B)
    #pragma unroll
    for (int i = 0; i < 5; i++) {
        int id = i * 256 + tid;
        int r = id / 10, c = id - r * 10;
        cp_async16(sb + r * SROW + c * 16, g_qh + (qkBase + m0 + r) * EP + c * 8);
    }
    cp_commit();

    auto load_kv = [&](int ic, int st) {
        uint32_t sbase = sb + FQ_SZ + st * F_STG;
        for (int lin = tid; lin < 640; lin += 256) {
            int r = lin / 10, c = lin - (lin / 10) * 10;   // K: 64 rows x 10 chunks
            cp_async16(sbase + FK_HI + r * SROW + c * 16,
                       g_kh + (qkBase + ic * 64 + r) * EP + c * 8);
        }
        for (int lin = tid; lin < 640; lin += 256) {
            int r = lin >> 3, c = lin & 7;                 // V: 80 rows x 8 chunks
            uint32_t so = (uint32_t)(r * 128) + (uint32_t)((c ^ (r & 7)) << 4);
            cp_async16(sbase + FV_HI + so,
                       g_vh + vBase + (size_t)r * SS + ic * 64 + c * 8);
        }
        cp_commit();
    };

    uint32_t qoff;
    {
        int khalf = lane >> 4;
        int r = wid * 16 + (lane & 15);
        qoff = (uint32_t)(r * SROW + khalf * 16);
    }
    uint32_t koff[4];
    {
        int idx = lane >> 3;
        int khalf = idx & 1;
        #pragma unroll
        for (int jp = 0; jp < 4; jp++) {
            int r = jp * 16 + (idx >> 1) * 8 + (lane & 7);
            koff[jp] = (uint32_t)(r * SROW + khalf * 16);
        }
    }
    uint32_t voff[5];
    {
        int idx = lane >> 3;
        int khalf = idx & 1;
        #pragma unroll
        for (int jp = 0; jp < 5; jp++) {
            int r = jp * 16 + (idx >> 1) * 8 + (lane & 7);
            voff[jp] = (uint32_t)(r * 128) + (uint32_t)((khalf ^ (r & 7)) << 4);
        }
    }

    float O[10][4];
    #pragma unroll
    for (int j = 0; j < 10; j++)
        #pragma unroll
        for (int q = 0; q < 4; q++) O[j][q] = 0.f;

    float scl = 2.0f / scale_p[0];
    load_kv(0, 0);

    for (int ic = 0; ic < 16; ic++) {
        int st = ic & 1;
        if (ic + 1 < 16) {
            load_kv(ic + 1, st ^ 1);
            cp_wait<1>();
        } else {
            cp_wait<0>();
        }
        __syncthreads();

        uint32_t kb = sb + FQ_SZ + st * F_STG;
        uint32_t qH = sb;
        uint32_t kH = kb + FK_HI;
        uint32_t vH = kb + FV_HI;

        // ---- S = Q K^T (16 rows x 64 cols per warp)
        float S[8][4];
        #pragma unroll
        for (int j = 0; j < 8; j++)
            #pragma unroll
            for (int q = 0; q < 4; q++) S[j][q] = 0.f;

        #pragma unroll
        for (int ks = 0; ks < 5; ks++) {
            uint32_t co = (uint32_t)(ks * 32);
            uint32_t Ah[4];
            ldsm_x4(Ah, qH + qoff + co);
            uint32_t Bh[8][2];
            #pragma unroll
            for (int jp = 0; jp < 4; jp++) {
                uint32_t r4[4];
                ldsm_x4(r4, kH + koff[jp] + co);
                Bh[jp * 2][0] = r4[0]; Bh[jp * 2][1] = r4[1];
                Bh[jp * 2 + 1][0] = r4[2]; Bh[jp * 2 + 1][1] = r4[3];
            }
            #pragma unroll
            for (int nj = 0; nj < 8; nj++)
                mma_f16(S[nj], Ah, Bh[nj]);
        }

        // ---- P = exp(S*scl); repack C-frags as A-frags; O += P V
        #pragma unroll
        for (int kc = 0; kc < 4; kc++) {
            float p[8];
            #pragma unroll
            for (int q = 0; q < 4; q++) {
                p[q]     = exp_fast(S[2 * kc][q] * scl);
                p[4 + q] = exp_fast(S[2 * kc + 1][q] * scl);
            }
            uint32_t Pah[4];
            Pah[0] = pack2h(p[0], p[1]);
            Pah[1] = pack2h(p[2], p[3]);
            Pah[2] = pack2h(p[4], p[5]);
            Pah[3] = pack2h(p[6], p[7]);
            uint32_t kso = (uint32_t)(kc * 32);
            uint32_t Vh[10][2];
            #pragma unroll
            for (int jp = 0; jp < 5; jp++) {
                uint32_t r4[4];
                ldsm_x4(r4, vH + (voff[jp] ^ kso));
                Vh[jp * 2][0] = r4[0]; Vh[jp * 2][1] = r4[1];
                Vh[jp * 2 + 1][0] = r4[2]; Vh[jp * 2 + 1][1] = r4[3];
            }
            #pragma unroll
            for (int nj = 0; nj < 10; nj++)
                mma_f16(O[nj], Pah, Vh[nj]);
        }
        __syncthreads();
    }

    // ---- in-register Lorentz project; write fp16 into gA_hi (cat layout)
    int g = lane >> 2, t = lane & 3;
    float s0 = 0.f, s1 = 0.f;
    #pragma unroll
    for (int nj = 0; nj < 10; nj++) {
        s0 += O[nj][0] * O[nj][0] + O[nj][1] * O[nj][1];
        s1 += O[nj][2] * O[nj][2] + O[nj][3] * O[nj][3];
    }
    s0 += __shfl_xor_sync(0xffffffffu, s0, 1);
    s0 += __shfl_xor_sync(0xffffffffu, s0, 2);
    s1 += __shfl_xor_sync(0xffffffffu, s1, 1);
    s1 += __shfl_xor_sync(0xffffffffu, s1, 2);
    float m00 = __shfl_sync(0xffffffffu, O[0][0], lane & ~3);
    float m01 = __shfl_sync(0xffffffffu, O[0][2], lane & ~3);
    float inv0 = rsqrtf(fmaxf(2.f * m00 * m00 - s0, 1e-6f));
    float inv1 = rsqrtf(fmaxf(2.f * m01 * m01 - s1, 1e-6f));

    int b = bh >> 4, h = bh & 15;
    int sq0 = m0 + wid * 16 + g;
    size_t r0 = (size_t)(b * SS + sq0) * KP1 + h * HD1;
    size_t r1 = (size_t)(b * SS + sq0 + 8) * KP1 + h * HD1;
    #pragma unroll
    for (int nj = 0; nj < 10; nj++) {
        int e = nj * 8 + 2 * t;
        #pragma unroll
        for (int q = 0; q < 2; q++) {
            if (e + q < 65) {
                gA_hi[r0 + e + q] = __float2half_rn(O[nj][q] * inv0);
                gA_hi[r1 + e + q] = __float2half_rn(O[nj][2 + q] * inv1);
            }
        }
    }
    if (h == 0) {
        for (int lin = tid; lin < 128 * 48; lin += 256) {
            int rr = lin / 48, cc = lin - (lin / 48) * 48;
            gA_hi[(size_t)(b * SS + m0 + rr) * KP1 + 1040 + cc] = __float2half_rn(0.f);
        }
    }
}

// ---------------- residual + project ------------------------------------------
__global__ void __launch_bounds__(256) resproj_k(const float* __restrict__ Xext,
                                                 int useInternalX,
                                                 const float* __restrict__ wp,
                                                 float* __restrict__ Oext,
                                                 int outInternal) {
    __shared__ float sm[8];
    const float* X = useInternalX ? g_x2 : Xext;
    float* out = outInternal ? g_x2 : Oext;
    int row = blockIdx.x;
    const float* ao = g_tmp + (size_t)row * DD;
    const float* xr = X + (size_t)row * D1;
    float a[4], sa = 0.f;
    #pragma unroll
    for (int i = 0; i < 4; i++) {
        a[i] = ao[threadIdx.x + i * 256];
        sa += a[i] * a[i];
    }
    sa = blockReduceSum(sa, sm);
    float w = wp[0];
    float tao = sqrtf(1.f + sa);
    float z0 = xr[0] + w * tao;
    float z[4], sz = 0.f;
    #pragma unroll
    for (int i = 0; i < 4; i++) {
        z[i] = xr[1 + threadIdx.x + i * 256] + w * a[i];
        sz += z[i] * z[i];
    }
    sz = blockReduceSum(sz, sm);
    float dinv = rsqrtf(fmaxf(z0 * z0 - sz, 1e-6f));
    float* orow = out + (size_t)row * D1;
    if (threadIdx.x == 0) orow[0] = z0 * dinv;
    #pragma unroll
    for (int i = 0; i < 4; i++) orow[1 + threadIdx.x + i * 256] = z[i] * dinv;
}

// ---------------- ff time component (reads gA2_hi, writes col0 + K-pad) -------
__global__ void __launch_bounds__(256) ffT_k() {
    __shared__ float sm[8];
    int row = blockIdx.x;
    size_t ob = (size_t)row * KP2;
    float ss = 0.f;
    #pragma unroll
    for (int i = 0; i < 16; i++) {
        float v = __half2float(gA2_hi[ob + 1 + threadIdx.x + i * 256]);
        ss += v * v;
    }
    ss = blockReduceSum(ss, sm);
    if (threadIdx.x == 0)
        gA2_hi[ob] = __float2half_rn(sqrtf(1.f + ss));
    if (threadIdx.x < KP2 - 4097)
        gA2_hi[ob + 4097 + threadIdx.x] = __float2half_rn(0.f);
}

// ---------------- launcher ----------------------------------------------------
extern "C" void kernel_launch(void* const* d_in, const int* in_sizes, int n_in,
                              void* d_out, int out_size) {
    const float* x      = (const float*)d_in[0];
    const float* rc     = (const float*)d_in[1];
    const float* rs     = (const float*)d_in[2];
    const float* n1g    = (const float*)d_in[3];
    const float* n1b    = (const float*)d_in[4];
    const float* Wq     = (const float*)d_in[5];
    const float* bq     = (const float*)d_in[6];
    const float* Wk     = (const float*)d_in[7];
    const float* bk     = (const float*)d_in[8];
    const float* Wv     = (const float*)d_in[9];
    const float* bv     = (const float*)d_in[10];
    const float* ascale = (const float*)d_in[11];
    const float* Wo     = (const float*)d_in[13];
    const float* bo     = (const float*)d_in[14];
    const float* wr1    = (const float*)d_in[15];
    const float* n2g    = (const float*)d_in[16];
    const float* n2b    = (const float*)d_in[17];
    const float* W1     = (const float*)d_in[18];
    const float* b1     = (const float*)d_in[19];
    const float* W2     = (const float*)d_in[20];
    const float* b2     = (const float*)d_in[21];
    const float* wr2    = (const float*)d_in[22];
    float* out = (float*)d_out;

    const int DSM   = 3 * STG;               // 98304 B
    const int DSM_F = FQ_SZ + 2 * F_STG;     // 65536 B
    cudaFuncSetAttribute(mmagemm_k<0>, cudaFuncAttributeMaxDynamicSharedMemorySize, DSM);
    cudaFuncSetAttribute(mmagemm_k<1>, cudaFuncAttributeMaxDynamicSharedMemorySize, DSM);
    cudaFuncSetAttribute(flash_k, cudaFuncAttributeMaxDynamicSharedMemorySize, DSM_F);

    const int BIG = 1 << 30;

    // ---- attention half ----
    ln_kernel<<<NROW, 256>>>(x, 0, n1g, n1b);
    transW_k<<<dim3(KP1 / 32, 32), 256>>>(Wq, 0,    D1, KP1, HDIM, D1 * HDIM, HDIM);
    transW_k<<<dim3(KP1 / 32, 32), 256>>>(Wk, 1024, D1, KP1, HDIM, D1 * HDIM, HDIM);
    transW_k<<<dim3(KP1 / 32, 32), 256>>>(Wv, 2048, D1, KP1, HDIM, D1 * HDIM, HDIM);
    mmagemm_k<0><<<dim3(24, 32), 256, DSM>>>(0, 0, bq, bk, bv, KP1, 3072, 1024);

    rope_k<<<24576, 256>>>(rc, rs);
    flash_k<<<dim3(8, 64), 256, DSM_F>>>(ascale);

    transW_k<<<dim3(KP1 / 32, 32), 256>>>(Wo, 0, CATW, KP1, DD, 0, DD);
    mmagemm_k<0><<<dim3(8, 32), 256, DSM>>>(0, 1, bo, bo, bo, KP1, DD, BIG);
    resproj_k<<<NROW, 256>>>(x, 0, wr1, nullptr, 1);

    // ---- MLP half ----
    ln_kernel<<<NROW, 256>>>(nullptr, 1, n2g, n2b);
    transW_k<<<dim3(KP1 / 32, FFDIM / 32), 256>>>(W1, 0, D1, KP1, FFDIM, 0, FFDIM);
    mmagemm_k<1><<<dim3(32, 32), 256, DSM>>>(0, 2, b1, b1, b1, KP1, KP2, BIG);
    ffT_k<<<NROW, 256>>>();

    transW_k<<<dim3(KP2 / 32, 32), 256>>>(W2, 0, FFDIM + 1, KP2, DD, 0, DD);
    mmagemm_k<0><<<dim3(8, 32), 256, DSM>>>(1, 1, b2, b2, b2, KP2, DD, BIG);
    resproj_k<<<NROW, 256>>>(nullptr, 1, wr2, out, 0);
}

// round 17
// speedup vs baseline: 1.8170x; 1.8170x over previous
#include <cuda_runtime.h>
#include <cuda_fp16.h>
#include <math.h>
#include <stdint.h>

#define SS 1024
#define DD 1024
#define HH 16
#define HDIM 64
#define FFDIM 4096
#define NROW 4096      // B*S
#define D1 1025
#define HD1 65
#define BHN 64         // B*H
#define CATW 1040      // H*(HD+1)
#define EP 80          // padded head-dim+1 (65 -> 80)
#define VE 80          // e-major V rows (65 data + 15 zero pad)

#define KP1 1088       // padded K (17*64)
#define KP2 4160       // padded K (65*64)

// ---------------- scratch (device globals; no allocation allowed) ----------
__device__ float g_qkv[NROW * 3072];
__device__ float g_tmp[NROW * DD];
__device__ float g_x2 [NROW * D1];

// fp16 buffers (single-term everywhere)
__device__ __align__(16) __half gA_hi [(size_t)NROW * KP1];
__device__ __align__(16) __half gA2_hi[(size_t)NROW * KP2];
__device__ __align__(16) __half gB_hi[(size_t)4096 * KP1];

// q (time-comp pre-negated), k: [bh][s][EP]
__device__ __align__(16) __half g_qh[(size_t)BHN * SS * EP];
__device__ __align__(16) __half g_kh[(size_t)BHN * SS * EP];

// V e-major: [bh][e(80)][s]
__device__ __align__(16) __half g_vh[(size_t)BHN * VE * SS];

// ---------------- small helpers ----------------------------------------------
__device__ __forceinline__ uint32_t smem_u32(const void* p) {
    uint32_t a;
    asm("{ .reg .u64 t; cvta.to.shared.u64 t, %1; cvt.u32.u64 %0, t; }"
        : "=r"(a) : "l"(p));
    return a;
}
__device__ __forceinline__ void cp_async16(uint32_t s, const void* g) {
    asm volatile("{ .reg .u64 gp; cvta.to.global.u64 gp, %1; "
                 "cp.async.cg.shared.global [%0], [gp], 16; }"
                 :: "r"(s), "l"(g) : "memory");
}
__device__ __forceinline__ void cp_commit() {
    asm volatile("cp.async.commit_group;" ::: "memory");
}
template<int N>
__device__ __forceinline__ void cp_wait() {
    asm volatile("cp.async.wait_group %0;" :: "n"(N) : "memory");
}
__device__ __forceinline__ void ldsm_x4(uint32_t* r, uint32_t addr) {
    asm volatile("ldmatrix.sync.aligned.m8n8.x4.shared.b16 {%0,%1,%2,%3}, [%4];"
                 : "=r"(r[0]), "=r"(r[1]), "=r"(r[2]), "=r"(r[3]) : "r"(addr));
}
__device__ __forceinline__ void mma_f16(float* c, const uint32_t* a, const uint32_t* b) {
    asm volatile("mma.sync.aligned.m16n8k16.row.col.f32.f16.f16.f32 "
                 "{%0,%1,%2,%3}, {%4,%5,%6,%7}, {%8,%9}, {%0,%1,%2,%3};"
                 : "+f"(c[0]), "+f"(c[1]), "+f"(c[2]), "+f"(c[3])
                 : "r"(a[0]), "r"(a[1]), "r"(a[2]), "r"(a[3]), "r"(b[0]), "r"(b[1]));
}
__device__ __forceinline__ uint32_t pack2h(float a, float b) {
    __half2 t;
    t.x = __float2half_rn(a);
    t.y = __float2half_rn(b);
    return *reinterpret_cast<uint32_t*>(&t);
}

// fast exp for logits in ~[-0.6, 0]
__device__ __forceinline__ float exp_fast(float x) {
    float t = fmaxf(x * 1.4426950408889634f, -100.f);
    float r = t + 12582912.0f;
    int ri = __float_as_int(r);
    float fi = r - 12582912.0f;
    float f = t - fi;
    float p = 0.00133335581f;
    p = fmaf(p, f, 0.00961812911f);
    p = fmaf(p, f, 0.05550410866f);
    p = fmaf(p, f, 0.24022650696f);
    p = fmaf(p, f, 0.69314718056f);
    p = fmaf(p, f, 1.0f);
    float s = __int_as_float((ri + 127) << 23);
    return p * s;
}

// ---------------- reductions --------------------------------------------------
__device__ __forceinline__ float blockReduceSum(float v, float* sm) {
    #pragma unroll
    for (int o = 16; o; o >>= 1) v += __shfl_xor_sync(0xffffffffu, v, o);
    int w = threadIdx.x >> 5;
    if ((threadIdx.x & 31) == 0) sm[w] = v;
    __syncthreads();
    if (threadIdx.x < 32) {
        float t = (threadIdx.x < 8) ? sm[threadIdx.x] : 0.f;
        #pragma unroll
        for (int o = 4; o; o >>= 1) t += __shfl_xor_sync(0xffffffffu, t, o);
        if (threadIdx.x == 0) sm[0] = t;
    }
    __syncthreads();
    float r = sm[0];
    __syncthreads();
    return r;
}
__device__ __forceinline__ float gelu_tanh(float x) {
    float x3 = x * x * x;
    float t = tanhf(0.7978845608028654f * (x + 0.044715f * x3));
    return 0.5f * x * (1.0f + t);
}

// ---------------- layernorm (writes fp16 gA_hi directly) ----------------------
__global__ void __launch_bounds__(256) ln_kernel(const float* __restrict__ Xext,
                                                 int useInternal,
                                                 const float* __restrict__ g,
                                                 const float* __restrict__ b) {
    __shared__ float sm[8];
    const float* X = useInternal ? g_x2 : Xext;
    int row = blockIdx.x;
    const float* xr = X + (size_t)row * D1 + 1;
    float v[4], s = 0.f, sq = 0.f;
    #pragma unroll
    for (int i = 0; i < 4; i++) {
        v[i] = xr[threadIdx.x + i * 256];
        s += v[i]; sq += v[i] * v[i];
    }
    s  = blockReduceSum(s,  sm);
    sq = blockReduceSum(sq, sm);
    float mu = s * (1.f / DD);
    float var = sq * (1.f / DD) - mu * mu;
    float rstd = rsqrtf(var + 1e-5f);
    float o[4], ss = 0.f;
    #pragma unroll
    for (int i = 0; i < 4; i++) {
        int c = threadIdx.x + i * 256;
        o[i] = (v[i] - mu) * rstd * g[c] + b[c];
        ss += o[i] * o[i];
    }
    ss = blockReduceSum(ss, sm);
    size_t ob = (size_t)row * KP1;
    if (threadIdx.x == 0)
        gA_hi[ob] = __float2half_rn(sqrtf(1.f + ss));
    #pragma unroll
    for (int i = 0; i < 4; i++)
        gA_hi[ob + 1 + threadIdx.x + i * 256] = __float2half_rn(o[i]);
    if (threadIdx.x < KP1 - 1025)
        gA_hi[ob + 1025 + threadIdx.x] = __float2half_rn(0.f);
}

// ---------------- weight transpose (fp16) -------------------------------------
__global__ void __launch_bounds__(256) transW_k(const float* __restrict__ src,
                                                int dstRow0, int K, int Kp,
                                                int strideK, int headStride,
                                                int headWidth) {
    __shared__ float t[32][33];
    int tx = threadIdx.x & 31, ty = threadIdx.x >> 5;
    int k0 = blockIdx.x * 32, n0 = blockIdx.y * 32;
    #pragma unroll
    for (int i = 0; i < 4; i++) {
        int k = k0 + ty + i * 8;
        int n = n0 + tx;
        float v = 0.f;
        if (k < K)
            v = src[(size_t)(n / headWidth) * headStride + (size_t)k * strideK + (n % headWidth)];
        t[ty + i * 8][tx] = v;
    }
    __syncthreads();
    #pragma unroll
    for (int i = 0; i < 4; i++) {
        int n = n0 + ty + i * 8;
        int k = k0 + tx;
        gB_hi[(size_t)(dstRow0 + n) * Kp + k] = __float2half_rn(t[tx][ty + i * 8]);
    }
}

// ---------------- warp-MMA fp16 GEMM (128x128 C tile, 3-stage, 2 CTA/SM) ------
#define TCS 16384
#define STG 32768
template<int EPI>
__global__ void __launch_bounds__(256, 2) mmagemm_k(
    int asel, int csel,
    const float* __restrict__ bias0, const float* __restrict__ bias1,
    const float* __restrict__ bias2,
    int Kp, int ldc, int nPerMat)
{
    extern __shared__ __align__(128) char dsm[];
    uint32_t sb0 = smem_u32(dsm);

    int tid = threadIdx.x;
    int wid = tid >> 5, lane = tid & 31;
    int wm = wid & 3, wn = wid >> 2;
    int m0 = blockIdx.y * 128, n0 = blockIdx.x * 128;

    int lchunk = tid & 7;
    int lrow = tid >> 3;

    const __half* Asrc = asel ? gA2_hi : gA_hi;
    const int NC = Kp >> 6;

    uint32_t aoff[2];
    {
        int khalf = lane >> 4;
        #pragma unroll
        for (int mi = 0; mi < 2; mi++) {
            int r = wm * 32 + mi * 16 + (lane & 15);
            aoff[mi] = (uint32_t)(r * 128) + (uint32_t)(((khalf) ^ (r & 7)) << 4);
        }
    }
    uint32_t boff[4];
    {
        int idx = lane >> 3;
        int khalf = idx & 1;
        #pragma unroll
        for (int jp = 0; jp < 4; jp++) {
            int r = wn * 64 + jp * 16 + (idx >> 1) * 8 + (lane & 7);
            boff[jp] = (uint32_t)(r * 128) + (uint32_t)((khalf ^ (r & 7)) << 4);
        }
    }

    float acc[2][8][4];
    #pragma unroll
    for (int i = 0; i < 2; i++)
        #pragma unroll
        for (int j = 0; j < 8; j++)
            #pragma unroll
            for (int q = 0; q < 4; q++) acc[i][j][q] = 0.f;

    auto load_stage = [&](int ic, int st) {
        size_t kbase = (size_t)ic * 64 + lchunk * 8;
        uint32_t sbase = sb0 + st * STG;
        #pragma unroll
        for (int i = 0; i < 4; i++) {
            int r = lrow + i * 32;
            uint32_t so = (uint32_t)(r * 128) + (uint32_t)((lchunk ^ (r & 7)) << 4);
            cp_async16(sbase + so, Asrc + (size_t)(m0 + r) * Kp + kbase);
            cp_async16(sbase + TCS + so, gB_hi + (size_t)(n0 + r) * Kp + kbase);
        }
        cp_commit();
    };

    load_stage(0, 0);
    if (NC > 1) load_stage(1, 1);

    int st = 0;
    for (int ic = 0; ic < NC; ic++) {
        if (ic + 2 < NC) {
            int st2 = (st + 2) % 3;
            load_stage(ic + 2, st2);
            cp_wait<2>();
        } else if (ic + 1 < NC) {
            cp_wait<1>();
        } else {
            cp_wait<0>();
        }
        __syncthreads();

        uint32_t aH = sb0 + st * STG;
        uint32_t bH = aH + TCS;

        #pragma unroll
        for (int ks = 0; ks < 4; ks++) {
            uint32_t kso = (uint32_t)(ks * 32);
            uint32_t Ah[2][4];
            #pragma unroll
            for (int mi = 0; mi < 2; mi++)
                ldsm_x4(Ah[mi], aH + (aoff[mi] ^ kso));
            uint32_t Bh[8][2];
            #pragma unroll
            for (int jp = 0; jp < 4; jp++) {
                uint32_t r4[4];
                ldsm_x4(r4, bH + (boff[jp] ^ kso));
                Bh[jp * 2][0] = r4[0]; Bh[jp * 2][1] = r4[1];
                Bh[jp * 2 + 1][0] = r4[2]; Bh[jp * 2 + 1][1] = r4[3];
            }
            #pragma unroll
            for (int mi = 0; mi < 2; mi++)
                #pragma unroll
                for (int nj = 0; nj < 8; nj++)
                    mma_f16(acc[mi][nj], Ah[mi], Bh[nj]);
        }
        __syncthreads();
        st = (st + 1) % 3;
    }

    int selB = (n0 / nPerMat);
    const float* bias = (selB == 0) ? bias0 : (selB == 1 ? bias1 : bias2);
    int nL0 = n0 - selB * nPerMat;

    int g = lane >> 2, t = lane & 3;
    if (csel == 2) {
        #pragma unroll
        for (int mi = 0; mi < 2; mi++) {
            int r0 = m0 + wm * 32 + mi * 16 + g;
            #pragma unroll
            for (int nj = 0; nj < 8; nj++) {
                int col = wn * 64 + nj * 8 + 2 * t;
                float b0 = bias[nL0 + col], b1 = bias[nL0 + col + 1];
                #pragma unroll
                for (int half = 0; half < 2; half++) {
                    float v0 = gelu_tanh(acc[mi][nj][half * 2 + 0] + b0);
                    float v1 = gelu_tanh(acc[mi][nj][half * 2 + 1] + b1);
                    size_t o = (size_t)(r0 + half * 8) * ldc + 1 + n0 + col;
                    gA2_hi[o] = __float2half_rn(v0);
                    gA2_hi[o + 1] = __float2half_rn(v1);
                }
            }
        }
    } else {
        float* C = (csel == 0) ? g_qkv : g_tmp;
        #pragma unroll
        for (int mi = 0; mi < 2; mi++) {
            int r0 = m0 + wm * 32 + mi * 16 + g;
            #pragma unroll
            for (int nj = 0; nj < 8; nj++) {
                int col = wn * 64 + nj * 8 + 2 * t;
                int cg = n0 + col;
                float b0 = bias[nL0 + col], b1 = bias[nL0 + col + 1];
                float* p0 = C + (size_t)r0 * ldc + cg;
                float* p1 = C + (size_t)(r0 + 8) * ldc + cg;
                p0[0] = acc[mi][nj][0] + b0; p0[1] = acc[mi][nj][1] + b1;
                p1[0] = acc[mi][nj][2] + b0; p1[1] = acc[mi][nj][3] + b1;
            }
        }
    }
}

// ---------------- RoPE + unit-norm + lift; q/k row-major, V e-major -----------
__global__ void __launch_bounds__(256) rope_k(const float* __restrict__ rc,
                                              const float* __restrict__ rs) {
    int gw = (blockIdx.x * 256 + threadIdx.x) >> 5;
    int lane = threadIdx.x & 31;
    int mat = gw / (NROW * HH);
    int rem = gw - mat * (NROW * HH);
    int row = rem >> 4;
    int h = rem & 15;
    int b = row >> 10, s = row & 1023;
    int bh = b * HH + h;
    const float* src = g_qkv + (size_t)row * 3072 + mat * 1024 + h * 64 + 2 * lane;
    float x0 = src[0], x1 = src[1];
    if (mat < 2) {
        float c = rc[s * 32 + lane], sn = rs[s * 32 + lane];
        float xr = x0 * c - x1 * sn;
        float xi = x0 * sn + x1 * c;
        float ss = xr * xr + xi * xi;
        #pragma unroll
        for (int o = 16; o; o >>= 1) ss += __shfl_xor_sync(0xffffffffu, ss, o);
        float inv = rsqrtf(ss + 1e-6f);
        float t = sqrtf(1.f + ss * inv * inv);
        __half* dh = ((mat == 0) ? g_qh : g_kh) + (size_t)(bh * SS + s) * EP;
        dh[1 + 2 * lane] = __float2half_rn(xr * inv);
        dh[2 + 2 * lane] = __float2half_rn(xi * inv);
        if (lane == 0) dh[0] = __float2half_rn((mat == 0) ? -t : t);
        if (lane < 15) dh[65 + lane] = __float2half_rn(0.f);
    } else {
        float ss = x0 * x0 + x1 * x1;
        #pragma unroll
        for (int o = 16; o; o >>= 1) ss += __shfl_xor_sync(0xffffffffu, ss, o);
        __half* vh = g_vh + (size_t)bh * VE * SS;
        vh[(size_t)(1 + 2 * lane) * SS + s] = __float2half_rn(x0);
        vh[(size_t)(2 + 2 * lane) * SS + s] = __float2half_rn(x1);
        if (lane == 0) vh[s] = __float2half_rn(sqrtf(1.f + ss));
        if (lane < 15) vh[(size_t)(65 + lane) * SS + s] = __float2half_rn(0.f);
    }
}

// ---------------- flash attention (single-term fp16, 2 CTA/SM) ----------------
#define SROW 176
#define FQ_SZ  22528                  // Q (128 x 176B)
#define FK_HI  0
#define FV_HI  11264
#define F_STG  21504                  // K (64x176) + V (80x128)
__global__ void __launch_bounds__(256, 2) flash_k(const float* __restrict__ scale_p) {
    extern __shared__ __align__(128) char dsm[];
    uint32_t sb = smem_u32(dsm);

    int tid = threadIdx.x;
    int wid = tid >> 5, lane = tid & 31;
    int bh = blockIdx.y;
    int m0 = blockIdx.x * 128;
    size_t qkBase = (size_t)bh * SS;
    size_t vBase = (size_t)bh * VE * SS;

    // load Q (128 rows x 160B, stride 176B)
    #pragma unroll
    for (int i = 0; i < 5; i++) {
        int id = i * 256 + tid;
        int r = id / 10, c = id - r * 10;
        cp_async16(sb + r * SROW + c * 16, g_qh + (qkBase + m0 + r) * EP + c * 8);
    }
    cp_commit();

    auto load_kv = [&](int ic, int st) {
        uint32_t sbase = sb + FQ_SZ + st * F_STG;
        for (int lin = tid; lin < 640; lin += 256) {
            int r = lin / 10, c = lin - (lin / 10) * 10;   // K: 64 rows x 10 chunks
            cp_async16(sbase + FK_HI + r * SROW + c * 16,
                       g_kh + (qkBase + ic * 64 + r) * EP + c * 8);
        }
        for (int lin = tid; lin < 640; lin += 256) {
            int r = lin >> 3, c = lin & 7;                 // V: 80 rows x 8 chunks
            uint32_t so = (uint32_t)(r * 128) + (uint32_t)((c ^ (r & 7)) << 4);
            cp_async16(sbase + FV_HI + so,
                       g_vh + vBase + (size_t)r * SS + ic * 64 + c * 8);
        }
        cp_commit();
    };

    uint32_t qoff;
    {
        int khalf = lane >> 4;
        int r = wid * 16 + (lane & 15);
        qoff = (uint32_t)(r * SROW + khalf * 16);
    }
    uint32_t koff[4];
    {
        int idx = lane >> 3;
        int khalf = idx & 1;
        #pragma unroll
        for (int jp = 0; jp < 4; jp++) {
            int r = jp * 16 + (idx >> 1) * 8 + (lane & 7);
            koff[jp] = (uint32_t)(r * SROW + khalf * 16);
        }
    }
    uint32_t voff[5];
    {
        int idx = lane >> 3;
        int khalf = idx & 1;
        #pragma unroll
        for (int jp = 0; jp < 5; jp++) {
            int r = jp * 16 + (idx >> 1) * 8 + (lane & 7);
            voff[jp] = (uint32_t)(r * 128) + (uint32_t)((khalf ^ (r & 7)) << 4);
        }
    }

    float O[10][4];
    #pragma unroll
    for (int j = 0; j < 10; j++)
        #pragma unroll
        for (int q = 0; q < 4; q++) O[j][q] = 0.f;

    float scl = 2.0f / scale_p[0];
    load_kv(0, 0);

    for (int ic = 0; ic < 16; ic++) {
        int st = ic & 1;
        if (ic + 1 < 16) {
            load_kv(ic + 1, st ^ 1);
            cp_wait<1>();
        } else {
            cp_wait<0>();
        }
        __syncthreads();

        uint32_t kb = sb + FQ_SZ + st * F_STG;
        uint32_t qH = sb;
        uint32_t kH = kb + FK_HI;
        uint32_t vH = kb + FV_HI;

        // ---- S = Q K^T (16 rows x 64 cols per warp)
        float S[8][4];
        #pragma unroll
        for (int j = 0; j < 8; j++)
            #pragma unroll
            for (int q = 0; q < 4; q++) S[j][q] = 0.f;

        #pragma unroll
        for (int ks = 0; ks < 5; ks++) {
            uint32_t co = (uint32_t)(ks * 32);
            uint32_t Ah[4];
            ldsm_x4(Ah, qH + qoff + co);
            uint32_t Bh[8][2];
            #pragma unroll
            for (int jp = 0; jp < 4; jp++) {
                uint32_t r4[4];
                ldsm_x4(r4, kH + koff[jp] + co);
                Bh[jp * 2][0] = r4[0]; Bh[jp * 2][1] = r4[1];
                Bh[jp * 2 + 1][0] = r4[2]; Bh[jp * 2 + 1][1] = r4[3];
            }
            #pragma unroll
            for (int nj = 0; nj < 8; nj++)
                mma_f16(S[nj], Ah, Bh[nj]);
        }

        // ---- P = exp(S*scl); repack C-frags as A-frags; O += P V
        #pragma unroll
        for (int kc = 0; kc < 4; kc++) {
            float p[8];
            #pragma unroll
            for (int q = 0; q < 4; q++) {
                p[q]     = exp_fast(S[2 * kc][q] * scl);
                p[4 + q] = exp_fast(S[2 * kc + 1][q] * scl);
            }
            uint32_t Pah[4];
            Pah[0] = pack2h(p[0], p[1]);
            Pah[1] = pack2h(p[2], p[3]);
            Pah[2] = pack2h(p[4], p[5]);
            Pah[3] = pack2h(p[6], p[7]);
            uint32_t kso = (uint32_t)(kc * 32);
            uint32_t Vh[10][2];
            #pragma unroll
            for (int jp = 0; jp < 5; jp++) {
                uint32_t r4[4];
                ldsm_x4(r4, vH + (voff[jp] ^ kso));
                Vh[jp * 2][0] = r4[0]; Vh[jp * 2][1] = r4[1];
                Vh[jp * 2 + 1][0] = r4[2]; Vh[jp * 2 + 1][1] = r4[3];
            }
            #pragma unroll
            for (int nj = 0; nj < 10; nj++)
                mma_f16(O[nj], Pah, Vh[nj]);
        }
        __syncthreads();
    }

    // ---- in-register Lorentz project; write fp16 into gA_hi (cat layout)
    int g = lane >> 2, t = lane & 3;
    float s0 = 0.f, s1 = 0.f;
    #pragma unroll
    for (int nj = 0; nj < 10; nj++) {
        s0 += O[nj][0] * O[nj][0] + O[nj][1] * O[nj][1];
        s1 += O[nj][2] * O[nj][2] + O[nj][3] * O[nj][3];
    }
    s0 += __shfl_xor_sync(0xffffffffu, s0, 1);
    s0 += __shfl_xor_sync(0xffffffffu, s0, 2);
    s1 += __shfl_xor_sync(0xffffffffu, s1, 1);
    s1 += __shfl_xor_sync(0xffffffffu, s1, 2);
    float m00 = __shfl_sync(0xffffffffu, O[0][0], lane & ~3);
    float m01 = __shfl_sync(0xffffffffu, O[0][2], lane & ~3);
    float inv0 = rsqrtf(fmaxf(2.f * m00 * m00 - s0, 1e-6f));
    float inv1 = rsqrtf(fmaxf(2.f * m01 * m01 - s1, 1e-6f));

    int b = bh >> 4, h = bh & 15;
    int sq0 = m0 + wid * 16 + g;
    size_t r0 = (size_t)(b * SS + sq0) * KP1 + h * HD1;
    size_t r1 = (size_t)(b * SS + sq0 + 8) * KP1 + h * HD1;
    #pragma unroll
    for (int nj = 0; nj < 10; nj++) {
        int e = nj * 8 + 2 * t;
        #pragma unroll
        for (int q = 0; q < 2; q++) {
            if (e + q < 65) {
                gA_hi[r0 + e + q] = __float2half_rn(O[nj][q] * inv0);
                gA_hi[r1 + e + q] = __float2half_rn(O[nj][2 + q] * inv1);
            }
        }
    }
    if (h == 0) {
        for (int lin = tid; lin < 128 * 48; lin += 256) {
            int rr = lin / 48, cc = lin - (lin / 48) * 48;
            gA_hi[(size_t)(b * SS + m0 + rr) * KP1 + 1040 + cc] = __float2half_rn(0.f);
        }
    }
}

// ---------------- residual + project ------------------------------------------
__global__ void __launch_bounds__(256) resproj_k(const float* __restrict__ Xext,
                                                 int useInternalX,
                                                 const float* __restrict__ wp,
                                                 float* __restrict__ Oext,
                                                 int outInternal) {
    __shared__ float sm[8];
    const float* X = useInternalX ? g_x2 : Xext;
    float* out = outInternal ? g_x2 : Oext;
    int row = blockIdx.x;
    const float* ao = g_tmp + (size_t)row * DD;
    const float* xr = X + (size_t)row * D1;
    float a[4], sa = 0.f;
    #pragma unroll
    for (int i = 0; i < 4; i++) {
        a[i] = ao[threadIdx.x + i * 256];
        sa += a[i] * a[i];
    }
    sa = blockReduceSum(sa, sm);
    float w = wp[0];
    float tao = sqrtf(1.f + sa);
    float z0 = xr[0] + w * tao;
    float z[4], sz = 0.f;
    #pragma unroll
    for (int i = 0; i < 4; i++) {
        z[i] = xr[1 + threadIdx.x + i * 256] + w * a[i];
        sz += z[i] * z[i];
    }
    sz = blockReduceSum(sz, sm);
    float dinv = rsqrtf(fmaxf(z0 * z0 - sz, 1e-6f));
    float* orow = out + (size_t)row * D1;
    if (threadIdx.x == 0) orow[0] = z0 * dinv;
    #pragma unroll
    for (int i = 0; i < 4; i++) orow[1 + threadIdx.x + i * 256] = z[i] * dinv;
}

// ---------------- ff time component (reads gA2_hi, writes col0 + K-pad) -------
__global__ void __launch_bounds__(256) ffT_k() {
    __shared__ float sm[8];
    int row = blockIdx.x;
    size_t ob = (size_t)row * KP2;
    float ss = 0.f;
    #pragma unroll
    for (int i = 0; i < 16; i++) {
        float v = __half2float(gA2_hi[ob + 1 + threadIdx.x + i * 256]);
        ss += v * v;
    }
    ss = blockReduceSum(ss, sm);
    if (threadIdx.x == 0)
        gA2_hi[ob] = __float2half_rn(sqrtf(1.f + ss));
    if (threadIdx.x < KP2 - 4097)
        gA2_hi[ob + 4097 + threadIdx.x] = __float2half_rn(0.f);
}

// ---------------- launcher ----------------------------------------------------
extern "C" void kernel_launch(void* const* d_in, const int* in_sizes, int n_in,
                              void* d_out, int out_size) {
    const float* x      = (const float*)d_in[0];
    const float* rc     = (const float*)d_in[1];
    const float* rs     = (const float*)d_in[2];
    const float* n1g    = (const float*)d_in[3];
    const float* n1b    = (const float*)d_in[4];
    const float* Wq     = (const float*)d_in[5];
    const float* bq     = (const float*)d_in[6];
    const float* Wk     = (const float*)d_in[7];
    const float* bk     = (const float*)d_in[8];
    const float* Wv     = (const float*)d_in[9];
    const float* bv     = (const float*)d_in[10];
    const float* ascale = (const float*)d_in[11];
    const float* Wo     = (const float*)d_in[13];
    const float* bo     = (const float*)d_in[14];
    const float* wr1    = (const float*)d_in[15];
    const float* n2g    = (const float*)d_in[16];
    const float* n2b    = (const float*)d_in[17];
    const float* W1     = (const float*)d_in[18];
    const float* b1     = (const float*)d_in[19];
    const float* W2     = (const float*)d_in[20];
    const float* b2     = (const float*)d_in[21];
    const float* wr2    = (const float*)d_in[22];
    float* out = (float*)d_out;

    const int DSM   = 3 * STG;               // 98304 B (x2 CTA = 192K/SM)
    const int DSM_F = FQ_SZ + 2 * F_STG;     // 65536 B (x2 CTA = 128K/SM)
    cudaFuncSetAttribute(mmagemm_k<0>, cudaFuncAttributeMaxDynamicSharedMemorySize, DSM);
    cudaFuncSetAttribute(mmagemm_k<1>, cudaFuncAttributeMaxDynamicSharedMemorySize, DSM);
    cudaFuncSetAttribute(flash_k, cudaFuncAttributeMaxDynamicSharedMemorySize, DSM_F);

    const int BIG = 1 << 30;

    // ---- attention half ----
    ln_kernel<<<NROW, 256>>>(x, 0, n1g, n1b);
    transW_k<<<dim3(KP1 / 32, 32), 256>>>(Wq, 0,    D1, KP1, HDIM, D1 * HDIM, HDIM);
    transW_k<<<dim3(KP1 / 32, 32), 256>>>(Wk, 1024, D1, KP1, HDIM, D1 * HDIM, HDIM);
    transW_k<<<dim3(KP1 / 32, 32), 256>>>(Wv, 2048, D1, KP1, HDIM, D1 * HDIM, HDIM);
    mmagemm_k<0><<<dim3(24, 32), 256, DSM>>>(0, 0, bq, bk, bv, KP1, 3072, 1024);

    rope_k<<<24576, 256>>>(rc, rs);
    flash_k<<<dim3(8, 64), 256, DSM_F>>>(ascale);

    transW_k<<<dim3(KP1 / 32, 32), 256>>>(Wo, 0, CATW, KP1, DD, 0, DD);
    mmagemm_k<0><<<dim3(8, 32), 256, DSM>>>(0, 1, bo, bo, bo, KP1, DD, BIG);
    resproj_k<<<NROW, 256>>>(x, 0, wr1, nullptr, 1);

    // ---- MLP half ----
    ln_kernel<<<NROW, 256>>>(nullptr, 1, n2g, n2b);
    transW_k<<<dim3(KP1 / 32, FFDIM / 32), 256>>>(W1, 0, D1, KP1, FFDIM, 0, FFDIM);
    mmagemm_k<1><<<dim3(32, 32), 256, DSM>>>(0, 2, b1, b1, b1, KP1, KP2, BIG);
    ffT_k<<<NROW, 256>>>();

    transW_k<<<dim3(KP2 / 32, 32), 256>>>(W2, 0, FFDIM + 1, KP2, DD, 0, DD);
    mmagemm_k<0><<<dim3(8, 32), 256, DSM>>>(1, 1, b2, b2, b2, KP2, DD, BIG);
    resproj_k<<<NROW, 256>>>(nullptr, 1, wr2, out, 0);
}